// round 11
// baseline (speedup 1.0000x reference)
#include <cuda_runtime.h>
#include <cuda_fp16.h>
#include <cuda_bf16.h>
#include <math.h>
#include <stdint.h>

#define N 8192
#define D 64
#define EPS 0.1f
#define INV_EPS 10.0f

// Scratch (device globals — no allocation allowed)
__device__ __half g_K[(size_t)N * (size_t)N];   // 128 MB kernel matrix (fp16)
__device__ float g_spn[N];
__device__ float g_sqn[N];
__device__ float g_pp[2][8][N];                 // ping-pong column-split partial sums
__device__ float g_part[N];

__device__ __forceinline__ float sqrt_approx(float x) {
    float r;
    asm("sqrt.approx.f32 %0, %1;" : "=f"(r) : "f"(x));
    return r;
}
__device__ __forceinline__ uint32_t smem_u32(const void* p) {
    uint32_t a;
    asm("{ .reg .u64 t; cvta.to.shared.u64 t, %1; cvt.u32.u64 %0, t; }" : "=r"(a) : "l"(p));
    return a;
}

// m16n8k16 bf16 HMMA (build kernel)
__device__ __forceinline__ void mma_bf16(float* d, const uint32_t* a, const uint32_t* b) {
    asm volatile(
        "mma.sync.aligned.m16n8k16.row.col.f32.bf16.bf16.f32 "
        "{%0,%1,%2,%3}, {%4,%5,%6,%7}, {%8,%9}, {%0,%1,%2,%3};"
        : "+f"(d[0]), "+f"(d[1]), "+f"(d[2]), "+f"(d[3])
        : "r"(a[0]), "r"(a[1]), "r"(a[2]), "r"(a[3]), "r"(b[0]), "r"(b[1]));
}
// m16n8k16 fp16 HMMA, fp32 accum (matvec)
__device__ __forceinline__ void mma_f16(float* d, const uint32_t* a, uint32_t b0, uint32_t b1) {
    asm volatile(
        "mma.sync.aligned.m16n8k16.row.col.f32.f16.f16.f32 "
        "{%0,%1,%2,%3}, {%4,%5,%6,%7}, {%8,%9}, {%0,%1,%2,%3};"
        : "+f"(d[0]), "+f"(d[1]), "+f"(d[2]), "+f"(d[3])
        : "r"(a[0]), "r"(a[1]), "r"(a[2]), "r"(a[3]), "r"(b0), "r"(b1));
}

// ---------------------------------------------------------------------------
// Row norms of P and Q: one warp per row
// ---------------------------------------------------------------------------
__global__ void norms_kernel(const float* __restrict__ P, const float* __restrict__ Q) {
    int w = (blockIdx.x * blockDim.x + threadIdx.x) >> 5;
    int lane = threadIdx.x & 31;
    if (w >= N) return;
    float2 p = reinterpret_cast<const float2*>(P)[w * 32 + lane];
    float s = p.x * p.x + p.y * p.y;
    float2 q = reinterpret_cast<const float2*>(Q)[w * 32 + lane];
    float t = q.x * q.x + q.y * q.y;
    #pragma unroll
    for (int o = 16; o > 0; o >>= 1) {
        s += __shfl_xor_sync(0xffffffffu, s, o);
        t += __shfl_xor_sync(0xffffffffu, t, o);
    }
    if (lane == 0) { g_spn[w] = s; g_sqn[w] = t; }
}

// Initialize partial-sum buffer 0 so consumers see x = 1/64 (u0).
__global__ void init_pp() {
    int i = blockIdx.x * blockDim.x + threadIdx.x;
    if (i < N) {
        g_pp[0][0][i] = 64.0f;
        #pragma unroll
        for (int c = 1; c < 8; c++) g_pp[0][c][i] = 0.0f;
    }
}

// ---------------------------------------------------------------------------
// Build K = exp(-sqrt(max(|p|^2+|q|^2-2 p.q, 0))/EPS) via mma.sync bf16.
// (unchanged from R10 — validated)
// ---------------------------------------------------------------------------
#define AST 72
#define CST 136

__global__ void __launch_bounds__(256)
build_kernel(const float* __restrict__ P, const float* __restrict__ Q) {
    __shared__ float s_norm[256];
    __shared__ __align__(16) char s_tile[2 * 128 * AST * 2];

    __nv_bfloat16* s_A = reinterpret_cast<__nv_bfloat16*>(s_tile);
    __nv_bfloat16* s_B = s_A + 128 * AST;

    const int tid = threadIdx.x;
    const int by = blockIdx.y, bx = blockIdx.x;

    if (tid < 128) s_norm[tid] = g_spn[by * 128 + tid];
    else           s_norm[tid] = g_sqn[bx * 128 + (tid - 128)];

    {
        const int row = tid >> 1, half = tid & 1;
        const float4* ps = reinterpret_cast<const float4*>(P + (size_t)(by * 128 + row) * D + half * 32);
        __nv_bfloat16* ad = s_A + row * AST + half * 32;
        #pragma unroll
        for (int s = 0; s < 4; s++) {
            float4 f0 = ps[2 * s], f1 = ps[2 * s + 1];
            __nv_bfloat162 hh[4];
            hh[0] = __floats2bfloat162_rn(f0.x, f0.y);
            hh[1] = __floats2bfloat162_rn(f0.z, f0.w);
            hh[2] = __floats2bfloat162_rn(f1.x, f1.y);
            hh[3] = __floats2bfloat162_rn(f1.z, f1.w);
            *reinterpret_cast<uint4*>(ad + s * 8) = *reinterpret_cast<uint4*>(hh);
        }
        const float4* qs = reinterpret_cast<const float4*>(Q + (size_t)(bx * 128 + row) * D + half * 32);
        __nv_bfloat16* bd = s_B + row * AST + half * 32;
        #pragma unroll
        for (int s = 0; s < 4; s++) {
            float4 f0 = qs[2 * s], f1 = qs[2 * s + 1];
            __nv_bfloat162 hh[4];
            hh[0] = __floats2bfloat162_rn(f0.x, f0.y);
            hh[1] = __floats2bfloat162_rn(f0.z, f0.w);
            hh[2] = __floats2bfloat162_rn(f1.x, f1.y);
            hh[3] = __floats2bfloat162_rn(f1.z, f1.w);
            *reinterpret_cast<uint4*>(bd + s * 8) = *reinterpret_cast<uint4*>(hh);
        }
    }
    __syncthreads();

    const int lane = tid & 31, wid = tid >> 5;
    const int g = lane >> 2, t = lane & 3;
    const int wm = (wid & 1) * 64;
    const int wn = (wid >> 1) * 32;

    float acc[4][4][4];
    #pragma unroll
    for (int mi = 0; mi < 4; mi++)
        #pragma unroll
        for (int nj = 0; nj < 4; nj++)
            #pragma unroll
            for (int e = 0; e < 4; e++) acc[mi][nj][e] = 0.0f;

    #pragma unroll
    for (int ks = 0; ks < 4; ks++) {
        const int kb = ks * 16 + t * 2;
        uint32_t afr[4][4];
        #pragma unroll
        for (int mi = 0; mi < 4; mi++) {
            const int r = wm + mi * 16 + g;
            afr[mi][0] = *reinterpret_cast<const uint32_t*>(s_A + r * AST + kb);
            afr[mi][1] = *reinterpret_cast<const uint32_t*>(s_A + (r + 8) * AST + kb);
            afr[mi][2] = *reinterpret_cast<const uint32_t*>(s_A + r * AST + kb + 8);
            afr[mi][3] = *reinterpret_cast<const uint32_t*>(s_A + (r + 8) * AST + kb + 8);
        }
        uint32_t bfr[4][2];
        #pragma unroll
        for (int nj = 0; nj < 4; nj++) {
            const int c = wn + nj * 8 + g;
            bfr[nj][0] = *reinterpret_cast<const uint32_t*>(s_B + c * AST + kb);
            bfr[nj][1] = *reinterpret_cast<const uint32_t*>(s_B + c * AST + kb + 8);
        }
        #pragma unroll
        for (int mi = 0; mi < 4; mi++)
            #pragma unroll
            for (int nj = 0; nj < 4; nj++)
                mma_bf16(acc[mi][nj], afr[mi], bfr[nj]);
    }

    __syncthreads();
    __half* Cs = reinterpret_cast<__half*>(s_tile);

    #pragma unroll
    for (int mi = 0; mi < 4; mi++) {
        const int r0 = wm + mi * 16 + g;
        const float spa = s_norm[r0];
        const float spb = s_norm[r0 + 8];
        #pragma unroll
        for (int nj = 0; nj < 4; nj++) {
            const int c0 = wn + nj * 8 + t * 2;
            const float sq0 = s_norm[128 + c0];
            const float sq1 = s_norm[128 + c0 + 1];
            const float* a = acc[mi][nj];
            float e0 = __expf(-INV_EPS * sqrt_approx(fmaxf(spa + sq0 - 2.0f * a[0], 0.0f)));
            float e1 = __expf(-INV_EPS * sqrt_approx(fmaxf(spa + sq1 - 2.0f * a[1], 0.0f)));
            float e2 = __expf(-INV_EPS * sqrt_approx(fmaxf(spb + sq0 - 2.0f * a[2], 0.0f)));
            float e3 = __expf(-INV_EPS * sqrt_approx(fmaxf(spb + sq1 - 2.0f * a[3], 0.0f)));
            __half2 h01 = __floats2half2_rn(e0, e1);
            __half2 h23 = __floats2half2_rn(e2, e3);
            *reinterpret_cast<uint32_t*>(Cs + r0 * CST + c0)       = *reinterpret_cast<uint32_t*>(&h01);
            *reinterpret_cast<uint32_t*>(Cs + (r0 + 8) * CST + c0) = *reinterpret_cast<uint32_t*>(&h23);
        }
    }
    __syncthreads();

    #pragma unroll
    for (int i = 0; i < 8; i++) {
        const int idx = i * 256 + tid;
        const int r = idx >> 4, c16 = idx & 15;
        uint4 v = *reinterpret_cast<uint4*>(Cs + r * CST + c16 * 8);
        *reinterpret_cast<uint4*>(g_K + (size_t)(by * 128 + r) * N + bx * 128 + c16 * 8) = v;
    }
}

// ---------------------------------------------------------------------------
// Tensor-core matvec: raw row sums s = K @ x, where x_j = 1/(sum of src
// partials). CTA = 4 warps x 16 rows = 64 rows, column split 1/8 of N.
// cp.async 4-stage pipeline -> ldmatrix -> mma(f16,f32 acc). Writes one
// partial per (cs,row); consumer folds the reciprocal.
// ---------------------------------------------------------------------------
#define CSPLIT 8
#define MV_COLS (N / CSPLIT)      // 1024
#define MV_NCHUNK (MV_COLS / 64)  // 16
#define STAGES 4

__global__ void __launch_bounds__(128, 6) matvec_kernel(int src, int dst) {
    __shared__ __align__(16) __half xh[MV_COLS];                 // 2 KB
    __shared__ __align__(16) __half tiles[4][STAGES][16 * 64];   // 32 KB

    const int tid = threadIdx.x;
    const int lane = tid & 31, w = tid >> 5;
    const int cs = blockIdx.x, rb = blockIdx.y;
    const int grow = rb * 64 + w * 16;
    const int colbase = cs * MV_COLS;

    // Stage x as fp16: x_j = 1 / (sum of CSPLIT partials)
    #pragma unroll
    for (int i = tid; i < MV_COLS / 4; i += 128) {
        const int f4 = cs * (MV_COLS / 4) + i;
        float4 sum = reinterpret_cast<const float4*>(g_pp[src][0])[f4];
        #pragma unroll
        for (int c = 1; c < CSPLIT; c++) {
            float4 p = reinterpret_cast<const float4*>(g_pp[src][c])[f4];
            sum.x += p.x; sum.y += p.y; sum.z += p.z; sum.w += p.w;
        }
        __half2 h0 = __floats2half2_rn(1.0f / sum.x, 1.0f / sum.y);
        __half2 h1 = __floats2half2_rn(1.0f / sum.z, 1.0f / sum.w);
        uint2 pk;
        pk.x = *reinterpret_cast<uint32_t*>(&h0);
        pk.y = *reinterpret_cast<uint32_t*>(&h1);
        reinterpret_cast<uint2*>(xh)[i] = pk;
    }

    // cp.async lane geometry: chunk = 16 rows x 64 cols (2 KB per warp)
    const int c16 = lane & 7;          // 16B segment within a 128B row
    const int rquad = lane >> 3;       // 0..3
    const uint32_t tbase = smem_u32(&tiles[w][0][0]);
    const char* gsrc[4];
    uint32_t dstoff[4];
    #pragma unroll
    for (int i = 0; i < 4; i++) {
        const int rl = i * 4 + rquad;
        gsrc[i] = reinterpret_cast<const char*>(g_K + (size_t)(grow + rl) * N + colbase + c16 * 8);
        dstoff[i] = rl * 128 + ((c16 ^ (rl & 7)) * 16);
    }

    // ldmatrix lane geometry
    const int lm_m = lane >> 3, lm_r = lane & 7;
    const int lrow = lm_r + (lm_m & 1) * 8;
    const int khalf = lm_m >> 1;

    const int g = lane >> 2, t = lane & 3;
    float acc[4] = {0.0f, 0.0f, 0.0f, 0.0f};

    __syncthreads();   // xh ready

    // Prologue: fill stages 0..2
    #pragma unroll
    for (int s = 0; s < STAGES - 1; s++) {
        #pragma unroll
        for (int i = 0; i < 4; i++)
            asm volatile("cp.async.cg.shared.global [%0], [%1], 16;"
                         :: "r"(tbase + s * 2048 + dstoff[i]), "l"(gsrc[i] + s * 128) : "memory");
        asm volatile("cp.async.commit_group;" ::: "memory");
    }

    for (int ch = 0; ch < MV_NCHUNK; ch++) {
        asm volatile("cp.async.wait_group %0;" :: "n"(STAGES - 2) : "memory");
        __syncthreads();

        const uint32_t stbase = tbase + (ch & (STAGES - 1)) * 2048;
        const int xb = ch * 64;
        #pragma unroll
        for (int s4 = 0; s4 < 4; s4++) {
            const int cc = 2 * s4 + khalf;
            uint32_t a[4];
            asm volatile("ldmatrix.sync.aligned.m8n8.x4.shared.b16 {%0,%1,%2,%3}, [%4];"
                         : "=r"(a[0]), "=r"(a[1]), "=r"(a[2]), "=r"(a[3])
                         : "r"(stbase + lrow * 128 + ((cc ^ (lrow & 7)) * 16)));
            uint32_t b0 = *reinterpret_cast<const uint32_t*>(&xh[xb + s4 * 16 + t * 2]);
            uint32_t b1 = *reinterpret_cast<const uint32_t*>(&xh[xb + s4 * 16 + t * 2 + 8]);
            mma_f16(acc, a, b0, b1);
        }

        const int nch = ch + STAGES - 1;
        if (nch < MV_NCHUNK) {
            const uint32_t ns = tbase + (nch & (STAGES - 1)) * 2048;
            #pragma unroll
            for (int i = 0; i < 4; i++)
                asm volatile("cp.async.cg.shared.global [%0], [%1], 16;"
                             :: "r"(ns + dstoff[i]), "l"(gsrc[i] + nch * 128) : "memory");
        }
        asm volatile("cp.async.commit_group;" ::: "memory");
    }

    // All 8 N-columns of C are identical; c0/c2 hold the full row sums.
    if (t == 0) {
        g_pp[dst][cs][grow + g] = acc[0];
        g_pp[dst][cs][grow + g + 8] = acc[2];
    }
}

// ---------------------------------------------------------------------------
// Fused last matvec + loss row-partials (scalar; needs per-element log).
//   x_j = 1/(sum partials of src);  s_i = sum K_ij x_j;
//   t_i = sum K_ij x_j * (-EPS ln K_ij);  g_part[i] = t_i / s_i
// ---------------------------------------------------------------------------
#define RPB 10
#define MV_GRID ((N + RPB - 1) / RPB)

__global__ void __launch_bounds__(256, 6) final_kernel(int src) {
    __shared__ float xs[4096];
    __shared__ float reds[RPB][8], redt[RPB][8];

    const int tid = threadIdx.x;
    const int row0 = blockIdx.x * RPB;

    float s[RPB], t[RPB];
    #pragma unroll
    for (int r = 0; r < RPB; r++) { s[r] = 0.0f; t[r] = 0.0f; }

    #pragma unroll
    for (int h = 0; h < 2; h++) {
        #pragma unroll
        for (int i = 0; i < 4; i++) {
            const int f4 = h * 1024 + i * 256 + tid;
            float4 sum = reinterpret_cast<const float4*>(g_pp[src][0])[f4];
            #pragma unroll
            for (int c = 1; c < CSPLIT; c++) {
                float4 p = reinterpret_cast<const float4*>(g_pp[src][c])[f4];
                sum.x += p.x; sum.y += p.y; sum.z += p.z; sum.w += p.w;
            }
            float4 xv;
            xv.x = 1.0f / sum.x; xv.y = 1.0f / sum.y;
            xv.z = 1.0f / sum.z; xv.w = 1.0f / sum.w;
            reinterpret_cast<float4*>(xs)[i * 256 + tid] = xv;
        }
        __syncthreads();

        #pragma unroll
        for (int it = 0; it < 2; it++) {
            const int j = h * 512 + it * 256 + tid;
            float xf[8];
            *reinterpret_cast<float4*>(&xf[0]) = *reinterpret_cast<float4*>(&xs[(it * 256 + tid) * 8]);
            *reinterpret_cast<float4*>(&xf[4]) = *reinterpret_cast<float4*>(&xs[(it * 256 + tid) * 8 + 4]);
            #pragma unroll
            for (int rb = 0; rb < 2; rb++) {
                uint4 raw[5];
                #pragma unroll
                for (int r = 0; r < 5; r++) {
                    int row = row0 + rb * 5 + r;
                    if (row > N - 1) row = N - 1;
                    raw[r] = reinterpret_cast<const uint4*>(g_K + (size_t)row * N)[j];
                }
                #pragma unroll
                for (int r = 0; r < 5; r++) {
                    const __half2* h2 = reinterpret_cast<const __half2*>(&raw[r]);
                    #pragma unroll
                    for (int e = 0; e < 4; e++) {
                        float2 kk = __half22float2(h2[e]);
                        float kv0 = kk.x * xf[2 * e];
                        float kv1 = kk.y * xf[2 * e + 1];
                        s[rb * 5 + r] += kv0 + kv1;
                        t[rb * 5 + r] += kv0 * (-EPS * __logf(fmaxf(kk.x, 1e-30f)))
                                       + kv1 * (-EPS * __logf(fmaxf(kk.y, 1e-30f)));
                    }
                }
            }
        }
        __syncthreads();
    }

    const int lane = tid & 31, wd = tid >> 5;
    #pragma unroll
    for (int r = 0; r < RPB; r++) {
        float a = s[r], b = t[r];
        #pragma unroll
        for (int o = 16; o > 0; o >>= 1) {
            a += __shfl_xor_sync(0xffffffffu, a, o);
            b += __shfl_xor_sync(0xffffffffu, b, o);
        }
        if (lane == 0) { reds[r][wd] = a; redt[r][wd] = b; }
    }
    __syncthreads();
    if (tid < RPB) {
        float st = 0.0f, tt = 0.0f;
        #pragma unroll
        for (int w = 0; w < 8; w++) { st += reds[tid][w]; tt += redt[tid][w]; }
        const int row = row0 + tid;
        if (row < N) g_part[row] = tt / st;
    }
}

__global__ void sum_kernel(float* __restrict__ out) {
    float a = 0.0f;
    for (int i = threadIdx.x; i < N; i += 1024) a += g_part[i];
    __shared__ float sm[32];
    #pragma unroll
    for (int o = 16; o > 0; o >>= 1) a += __shfl_xor_sync(0xffffffffu, a, o);
    if ((threadIdx.x & 31) == 0) sm[threadIdx.x >> 5] = a;
    __syncthreads();
    if (threadIdx.x == 0) {
        float total = 0.0f;
        #pragma unroll
        for (int w = 0; w < 32; w++) total += sm[w];
        out[0] = total;
    }
}

// ---------------------------------------------------------------------------
extern "C" void kernel_launch(void* const* d_in, const int* in_sizes, int n_in,
                              void* d_out, int out_size) {
    (void)in_sizes; (void)n_in; (void)out_size;
    const float* P = (const float*)d_in[0];
    const float* Q = (const float*)d_in[1];
    float* out = (float*)d_out;

    norms_kernel<<<N / 8, 256>>>(P, Q);
    init_pp<<<N / 256, 256>>>();
    build_kernel<<<dim3(N / 128, N / 128), 256>>>(P, Q);

    // 9 tensor-core matvecs, ping-ponging partial buffers.
    for (int li = 0; li < 9; li++)
        matvec_kernel<<<dim3(CSPLIT, N / 64), 128>>>(li & 1, (li + 1) & 1);

    final_kernel<<<MV_GRID, 256>>>(1);   // last dst = (8+1)&1 = 1
    sum_kernel<<<1, 1024>>>(out);
}

// round 12
// speedup vs baseline: 1.5259x; 1.5259x over previous
#include <cuda_runtime.h>
#include <cuda_fp16.h>
#include <cuda_bf16.h>
#include <math.h>
#include <stdint.h>

#define N 8192
#define D 64
#define EPS 0.1f
#define INV_EPS 10.0f

// Scratch (device globals — no allocation allowed)
__device__ __half g_K[(size_t)N * (size_t)N];      // 128 MB fp16 K (final kernel)
__device__ uint8_t g_K8[(size_t)N * (size_t)N];    // 64 MB e4m3 K*256 (matvecs, L2-resident)
__device__ float g_spn[N];
__device__ float g_sqn[N];
__device__ float g_pp[2][8][N];                    // ping-pong column-split partials
__device__ float g_part[N];

__device__ __forceinline__ float sqrt_approx(float x) {
    float r;
    asm("sqrt.approx.f32 %0, %1;" : "=f"(r) : "f"(x));
    return r;
}
__device__ __forceinline__ uint32_t smem_u32(const void* p) {
    uint32_t a;
    asm("{ .reg .u64 t; cvta.to.shared.u64 t, %1; cvt.u32.u64 %0, t; }" : "=r"(a) : "l"(p));
    return a;
}
__device__ __forceinline__ uint16_t f2_e4m3x2(float hi, float lo) {
    uint16_t d;
    asm("cvt.rn.satfinite.e4m3x2.f32 %0, %1, %2;" : "=h"(d) : "f"(hi), "f"(lo));
    return d;
}

// m16n8k16 bf16 HMMA (build)
__device__ __forceinline__ void mma_bf16(float* d, const uint32_t* a, const uint32_t* b) {
    asm volatile(
        "mma.sync.aligned.m16n8k16.row.col.f32.bf16.bf16.f32 "
        "{%0,%1,%2,%3}, {%4,%5,%6,%7}, {%8,%9}, {%0,%1,%2,%3};"
        : "+f"(d[0]), "+f"(d[1]), "+f"(d[2]), "+f"(d[3])
        : "r"(a[0]), "r"(a[1]), "r"(a[2]), "r"(a[3]), "r"(b[0]), "r"(b[1]));
}
// m16n8k32 e4m3 MMA, fp32 accum (matvec) — sm_89+ base-arch instruction
__device__ __forceinline__ void mma_e4m3(float* d, const uint32_t* a, uint32_t b0, uint32_t b1) {
    asm volatile(
        "mma.sync.aligned.m16n8k32.row.col.f32.e4m3.e4m3.f32 "
        "{%0,%1,%2,%3}, {%4,%5,%6,%7}, {%8,%9}, {%0,%1,%2,%3};"
        : "+f"(d[0]), "+f"(d[1]), "+f"(d[2]), "+f"(d[3])
        : "r"(a[0]), "r"(a[1]), "r"(a[2]), "r"(a[3]), "r"(b0), "r"(b1));
}

// ---------------------------------------------------------------------------
__global__ void norms_kernel(const float* __restrict__ P, const float* __restrict__ Q) {
    int w = (blockIdx.x * blockDim.x + threadIdx.x) >> 5;
    int lane = threadIdx.x & 31;
    if (w >= N) return;
    float2 p = reinterpret_cast<const float2*>(P)[w * 32 + lane];
    float s = p.x * p.x + p.y * p.y;
    float2 q = reinterpret_cast<const float2*>(Q)[w * 32 + lane];
    float t = q.x * q.x + q.y * q.y;
    #pragma unroll
    for (int o = 16; o > 0; o >>= 1) {
        s += __shfl_xor_sync(0xffffffffu, s, o);
        t += __shfl_xor_sync(0xffffffffu, t, o);
    }
    if (lane == 0) { g_spn[w] = s; g_sqn[w] = t; }
}

__global__ void init_pp() {
    int i = blockIdx.x * blockDim.x + threadIdx.x;
    if (i < N) {
        g_pp[0][0][i] = 64.0f;
        #pragma unroll
        for (int c = 1; c < 8; c++) g_pp[0][c][i] = 0.0f;
    }
}

// ---------------------------------------------------------------------------
// Build K via mma.sync bf16; emit fp16 K (for final) and e4m3 K*256 (matvecs).
// ---------------------------------------------------------------------------
#define AST 72
#define CST 136
#define C8ST 144   // fp8 stage stride (bytes), 16-aligned

__global__ void __launch_bounds__(256)
build_kernel(const float* __restrict__ P, const float* __restrict__ Q) {
    __shared__ float s_norm[256];
    __shared__ __align__(16) char s_tile[2 * 128 * AST * 2];   // 36864 B
    __shared__ __align__(16) char s_c8[128 * C8ST];            // 18432 B

    __nv_bfloat16* s_A = reinterpret_cast<__nv_bfloat16*>(s_tile);
    __nv_bfloat16* s_B = s_A + 128 * AST;

    const int tid = threadIdx.x;
    const int by = blockIdx.y, bx = blockIdx.x;

    if (tid < 128) s_norm[tid] = g_spn[by * 128 + tid];
    else           s_norm[tid] = g_sqn[bx * 128 + (tid - 128)];

    {
        const int row = tid >> 1, half = tid & 1;
        const float4* ps = reinterpret_cast<const float4*>(P + (size_t)(by * 128 + row) * D + half * 32);
        __nv_bfloat16* ad = s_A + row * AST + half * 32;
        #pragma unroll
        for (int s = 0; s < 4; s++) {
            float4 f0 = ps[2 * s], f1 = ps[2 * s + 1];
            __nv_bfloat162 hh[4];
            hh[0] = __floats2bfloat162_rn(f0.x, f0.y);
            hh[1] = __floats2bfloat162_rn(f0.z, f0.w);
            hh[2] = __floats2bfloat162_rn(f1.x, f1.y);
            hh[3] = __floats2bfloat162_rn(f1.z, f1.w);
            *reinterpret_cast<uint4*>(ad + s * 8) = *reinterpret_cast<uint4*>(hh);
        }
        const float4* qs = reinterpret_cast<const float4*>(Q + (size_t)(bx * 128 + row) * D + half * 32);
        __nv_bfloat16* bd = s_B + row * AST + half * 32;
        #pragma unroll
        for (int s = 0; s < 4; s++) {
            float4 f0 = qs[2 * s], f1 = qs[2 * s + 1];
            __nv_bfloat162 hh[4];
            hh[0] = __floats2bfloat162_rn(f0.x, f0.y);
            hh[1] = __floats2bfloat162_rn(f0.z, f0.w);
            hh[2] = __floats2bfloat162_rn(f1.x, f1.y);
            hh[3] = __floats2bfloat162_rn(f1.z, f1.w);
            *reinterpret_cast<uint4*>(bd + s * 8) = *reinterpret_cast<uint4*>(hh);
        }
    }
    __syncthreads();

    const int lane = tid & 31, wid = tid >> 5;
    const int g = lane >> 2, t = lane & 3;
    const int wm = (wid & 1) * 64;
    const int wn = (wid >> 1) * 32;

    float acc[4][4][4];
    #pragma unroll
    for (int mi = 0; mi < 4; mi++)
        #pragma unroll
        for (int nj = 0; nj < 4; nj++)
            #pragma unroll
            for (int e = 0; e < 4; e++) acc[mi][nj][e] = 0.0f;

    #pragma unroll
    for (int ks = 0; ks < 4; ks++) {
        const int kb = ks * 16 + t * 2;
        uint32_t afr[4][4];
        #pragma unroll
        for (int mi = 0; mi < 4; mi++) {
            const int r = wm + mi * 16 + g;
            afr[mi][0] = *reinterpret_cast<const uint32_t*>(s_A + r * AST + kb);
            afr[mi][1] = *reinterpret_cast<const uint32_t*>(s_A + (r + 8) * AST + kb);
            afr[mi][2] = *reinterpret_cast<const uint32_t*>(s_A + r * AST + kb + 8);
            afr[mi][3] = *reinterpret_cast<const uint32_t*>(s_A + (r + 8) * AST + kb + 8);
        }
        uint32_t bfr[4][2];
        #pragma unroll
        for (int nj = 0; nj < 4; nj++) {
            const int c = wn + nj * 8 + g;
            bfr[nj][0] = *reinterpret_cast<const uint32_t*>(s_B + c * AST + kb);
            bfr[nj][1] = *reinterpret_cast<const uint32_t*>(s_B + c * AST + kb + 8);
        }
        #pragma unroll
        for (int mi = 0; mi < 4; mi++)
            #pragma unroll
            for (int nj = 0; nj < 4; nj++)
                mma_bf16(acc[mi][nj], afr[mi], bfr[nj]);
    }

    __syncthreads();
    __half* Cs = reinterpret_cast<__half*>(s_tile);

    #pragma unroll
    for (int mi = 0; mi < 4; mi++) {
        const int r0 = wm + mi * 16 + g;
        const float spa = s_norm[r0];
        const float spb = s_norm[r0 + 8];
        #pragma unroll
        for (int nj = 0; nj < 4; nj++) {
            const int c0 = wn + nj * 8 + t * 2;
            const float sq0 = s_norm[128 + c0];
            const float sq1 = s_norm[128 + c0 + 1];
            const float* a = acc[mi][nj];
            float e0 = __expf(-INV_EPS * sqrt_approx(fmaxf(spa + sq0 - 2.0f * a[0], 0.0f)));
            float e1 = __expf(-INV_EPS * sqrt_approx(fmaxf(spa + sq1 - 2.0f * a[1], 0.0f)));
            float e2 = __expf(-INV_EPS * sqrt_approx(fmaxf(spb + sq0 - 2.0f * a[2], 0.0f)));
            float e3 = __expf(-INV_EPS * sqrt_approx(fmaxf(spb + sq1 - 2.0f * a[3], 0.0f)));
            __half2 h01 = __floats2half2_rn(e0, e1);
            __half2 h23 = __floats2half2_rn(e2, e3);
            *reinterpret_cast<uint32_t*>(Cs + r0 * CST + c0)       = *reinterpret_cast<uint32_t*>(&h01);
            *reinterpret_cast<uint32_t*>(Cs + (r0 + 8) * CST + c0) = *reinterpret_cast<uint32_t*>(&h23);
            // fp8 copy: K*256, pair-packed {lo=e0, hi=e1}
            *reinterpret_cast<uint16_t*>(s_c8 + r0 * C8ST + c0)       = f2_e4m3x2(e1 * 256.0f, e0 * 256.0f);
            *reinterpret_cast<uint16_t*>(s_c8 + (r0 + 8) * C8ST + c0) = f2_e4m3x2(e3 * 256.0f, e2 * 256.0f);
        }
    }
    __syncthreads();

    // fp16 store: 2048 uint4
    #pragma unroll
    for (int i = 0; i < 8; i++) {
        const int idx = i * 256 + tid;
        const int r = idx >> 4, c16 = idx & 15;
        uint4 v = *reinterpret_cast<uint4*>(Cs + r * CST + c16 * 8);
        *reinterpret_cast<uint4*>(g_K + (size_t)(by * 128 + r) * N + bx * 128 + c16 * 8) = v;
    }
    // fp8 store: 1024 uint4
    #pragma unroll
    for (int i = 0; i < 4; i++) {
        const int idx = i * 256 + tid;
        const int r = idx >> 3, seg = idx & 7;
        uint4 v = *reinterpret_cast<uint4*>(s_c8 + r * C8ST + seg * 16);
        *reinterpret_cast<uint4*>(g_K8 + (size_t)(by * 128 + r) * N + bx * 128 + seg * 16) = v;
    }
}

// ---------------------------------------------------------------------------
// fp8 tensor-core matvec on the L2-resident K8. CTA = 4 warps x 16 rows,
// column split 1/8. Chunk = 16 rows x 128 fp8 (2 KB/warp/stage), 4 k-steps
// of 32 per chunk. acc scale = 1/(256*64).
// ---------------------------------------------------------------------------
#define CSPLIT 8
#define MV_COLS (N / CSPLIT)        // 1024 fp8 cols per block
#define MV_NCHUNK (MV_COLS / 128)   // 8
#define STAGES 4

__global__ void __launch_bounds__(128, 6) matvec_kernel(int src, int dst) {
    __shared__ __align__(16) uint8_t xh8[MV_COLS];               // 1 KB e4m3 x*64
    __shared__ __align__(16) uint8_t tiles[4][STAGES][16 * 128]; // 32 KB

    const int tid = threadIdx.x;
    const int lane = tid & 31, w = tid >> 5;
    const int cs = blockIdx.x, rb = blockIdx.y;
    const int grow = rb * 64 + w * 16;
    const int colbase = cs * MV_COLS;

    // Stage x as e4m3: x_j = 64 / (sum of CSPLIT partials)
    #pragma unroll
    for (int i = tid; i < MV_COLS / 4; i += 128) {
        const int f4 = cs * (MV_COLS / 4) + i;
        float4 sum = reinterpret_cast<const float4*>(g_pp[src][0])[f4];
        #pragma unroll
        for (int c = 1; c < CSPLIT; c++) {
            float4 p = reinterpret_cast<const float4*>(g_pp[src][c])[f4];
            sum.x += p.x; sum.y += p.y; sum.z += p.z; sum.w += p.w;
        }
        uint16_t lo = f2_e4m3x2(64.0f / sum.y, 64.0f / sum.x);
        uint16_t hi = f2_e4m3x2(64.0f / sum.w, 64.0f / sum.z);
        reinterpret_cast<uint32_t*>(xh8)[i] = (uint32_t)lo | ((uint32_t)hi << 16);
    }

    // cp.async geometry: chunk = 16 rows x 128 B
    const int c16 = lane & 7;
    const int rquad = lane >> 3;
    const uint32_t tbase = smem_u32(&tiles[w][0][0]);
    const char* gsrc[4];
    uint32_t dstoff[4];
    #pragma unroll
    for (int i = 0; i < 4; i++) {
        const int rl = i * 4 + rquad;
        gsrc[i] = reinterpret_cast<const char*>(g_K8 + (size_t)(grow + rl) * N + colbase + c16 * 16);
        dstoff[i] = rl * 128 + ((c16 ^ (rl & 7)) * 16);
    }

    // ldmatrix geometry (b16 path; 1 b16 = 2 fp8 along k)
    const int lm_m = lane >> 3, lm_r = lane & 7;
    const int lrow = lm_r + (lm_m & 1) * 8;
    const int khalf = lm_m >> 1;

    const int g = lane >> 2, t = lane & 3;
    float acc[4] = {0.0f, 0.0f, 0.0f, 0.0f};

    __syncthreads();   // xh8 ready

    #pragma unroll
    for (int s = 0; s < STAGES - 1; s++) {
        #pragma unroll
        for (int i = 0; i < 4; i++)
            asm volatile("cp.async.cg.shared.global [%0], [%1], 16;"
                         :: "r"(tbase + s * 2048 + dstoff[i]), "l"(gsrc[i] + s * 128) : "memory");
        asm volatile("cp.async.commit_group;" ::: "memory");
    }

    for (int ch = 0; ch < MV_NCHUNK; ch++) {
        asm volatile("cp.async.wait_group %0;" :: "n"(STAGES - 2) : "memory");
        __syncthreads();

        const uint32_t stbase = tbase + (ch & (STAGES - 1)) * 2048;
        const int xb = ch * 128;
        #pragma unroll
        for (int s4 = 0; s4 < 4; s4++) {     // k-step of 32 fp8 = 2 16B segs
            const int cc = 2 * s4 + khalf;
            uint32_t a[4];
            asm volatile("ldmatrix.sync.aligned.m8n8.x4.shared.b16 {%0,%1,%2,%3}, [%4];"
                         : "=r"(a[0]), "=r"(a[1]), "=r"(a[2]), "=r"(a[3])
                         : "r"(stbase + lrow * 128 + ((cc ^ (lrow & 7)) * 16)));
            uint32_t b0 = *reinterpret_cast<const uint32_t*>(&xh8[xb + s4 * 32 + t * 4]);
            uint32_t b1 = *reinterpret_cast<const uint32_t*>(&xh8[xb + s4 * 32 + t * 4 + 16]);
            mma_e4m3(acc, a, b0, b1);
        }

        const int nch = ch + STAGES - 1;
        if (nch < MV_NCHUNK) {
            const uint32_t ns = tbase + (nch & (STAGES - 1)) * 2048;
            #pragma unroll
            for (int i = 0; i < 4; i++)
                asm volatile("cp.async.cg.shared.global [%0], [%1], 16;"
                             :: "r"(ns + dstoff[i]), "l"(gsrc[i] + nch * 128) : "memory");
        }
        asm volatile("cp.async.commit_group;" ::: "memory");
    }

    // Columns identical -> acc[0]/acc[2] are the row sums (scaled by 256*64)
    if (t == 0) {
        const float s = 1.0f / 16384.0f;
        g_pp[dst][cs][grow + g]     = acc[0] * s;
        g_pp[dst][cs][grow + g + 8] = acc[2] * s;
    }
}

// ---------------------------------------------------------------------------
// Fused last matvec + loss row-partials (fp16 K path, unchanged precision).
// ---------------------------------------------------------------------------
#define RPB 10
#define MV_GRID ((N + RPB - 1) / RPB)

__global__ void __launch_bounds__(256, 6) final_kernel(int src) {
    __shared__ float xs[4096];
    __shared__ float reds[RPB][8], redt[RPB][8];

    const int tid = threadIdx.x;
    const int row0 = blockIdx.x * RPB;

    float s[RPB], t[RPB];
    #pragma unroll
    for (int r = 0; r < RPB; r++) { s[r] = 0.0f; t[r] = 0.0f; }

    #pragma unroll
    for (int h = 0; h < 2; h++) {
        #pragma unroll
        for (int i = 0; i < 4; i++) {
            const int f4 = h * 1024 + i * 256 + tid;
            float4 sum = reinterpret_cast<const float4*>(g_pp[src][0])[f4];
            #pragma unroll
            for (int c = 1; c < CSPLIT; c++) {
                float4 p = reinterpret_cast<const float4*>(g_pp[src][c])[f4];
                sum.x += p.x; sum.y += p.y; sum.z += p.z; sum.w += p.w;
            }
            float4 xv;
            xv.x = 1.0f / sum.x; xv.y = 1.0f / sum.y;
            xv.z = 1.0f / sum.z; xv.w = 1.0f / sum.w;
            reinterpret_cast<float4*>(xs)[i * 256 + tid] = xv;
        }
        __syncthreads();

        #pragma unroll
        for (int it = 0; it < 2; it++) {
            const int j = h * 512 + it * 256 + tid;
            float xf[8];
            *reinterpret_cast<float4*>(&xf[0]) = *reinterpret_cast<float4*>(&xs[(it * 256 + tid) * 8]);
            *reinterpret_cast<float4*>(&xf[4]) = *reinterpret_cast<float4*>(&xs[(it * 256 + tid) * 8 + 4]);
            #pragma unroll
            for (int rb = 0; rb < 2; rb++) {
                uint4 raw[5];
                #pragma unroll
                for (int r = 0; r < 5; r++) {
                    int row = row0 + rb * 5 + r;
                    if (row > N - 1) row = N - 1;
                    raw[r] = reinterpret_cast<const uint4*>(g_K + (size_t)row * N)[j];
                }
                #pragma unroll
                for (int r = 0; r < 5; r++) {
                    const __half2* h2 = reinterpret_cast<const __half2*>(&raw[r]);
                    #pragma unroll
                    for (int e = 0; e < 4; e++) {
                        float2 kk = __half22float2(h2[e]);
                        float kv0 = kk.x * xf[2 * e];
                        float kv1 = kk.y * xf[2 * e + 1];
                        s[rb * 5 + r] += kv0 + kv1;
                        t[rb * 5 + r] += kv0 * (-EPS * __logf(fmaxf(kk.x, 1e-30f)))
                                       + kv1 * (-EPS * __logf(fmaxf(kk.y, 1e-30f)));
                    }
                }
            }
        }
        __syncthreads();
    }

    const int lane = tid & 31, wd = tid >> 5;
    #pragma unroll
    for (int r = 0; r < RPB; r++) {
        float a = s[r], b = t[r];
        #pragma unroll
        for (int o = 16; o > 0; o >>= 1) {
            a += __shfl_xor_sync(0xffffffffu, a, o);
            b += __shfl_xor_sync(0xffffffffu, b, o);
        }
        if (lane == 0) { reds[r][wd] = a; redt[r][wd] = b; }
    }
    __syncthreads();
    if (tid < RPB) {
        float st = 0.0f, tt = 0.0f;
        #pragma unroll
        for (int w = 0; w < 8; w++) { st += reds[tid][w]; tt += redt[tid][w]; }
        const int row = row0 + tid;
        if (row < N) g_part[row] = tt / st;
    }
}

__global__ void sum_kernel(float* __restrict__ out) {
    float a = 0.0f;
    for (int i = threadIdx.x; i < N; i += 1024) a += g_part[i];
    __shared__ float sm[32];
    #pragma unroll
    for (int o = 16; o > 0; o >>= 1) a += __shfl_xor_sync(0xffffffffu, a, o);
    if ((threadIdx.x & 31) == 0) sm[threadIdx.x >> 5] = a;
    __syncthreads();
    if (threadIdx.x == 0) {
        float total = 0.0f;
        #pragma unroll
        for (int w = 0; w < 32; w++) total += sm[w];
        out[0] = total;
    }
}

// ---------------------------------------------------------------------------
extern "C" void kernel_launch(void* const* d_in, const int* in_sizes, int n_in,
                              void* d_out, int out_size) {
    (void)in_sizes; (void)n_in; (void)out_size;
    const float* P = (const float*)d_in[0];
    const float* Q = (const float*)d_in[1];
    float* out = (float*)d_out;

    norms_kernel<<<N / 8, 256>>>(P, Q);
    init_pp<<<N / 256, 256>>>();
    build_kernel<<<dim3(N / 128, N / 128), 256>>>(P, Q);

    for (int li = 0; li < 9; li++)
        matvec_kernel<<<dim3(CSPLIT, N / 64), 128>>>(li & 1, (li + 1) & 1);

    final_kernel<<<MV_GRID, 256>>>(1);
    sum_kernel<<<1, 1024>>>(out);
}

// round 13
// speedup vs baseline: 1.6948x; 1.1107x over previous
#include <cuda_runtime.h>
#include <cuda_fp16.h>
#include <cuda_bf16.h>
#include <math.h>
#include <stdint.h>

#define N 8192
#define D 64
#define EPS 0.1f
#define INV_EPS 10.0f

// Scratch (device globals — no allocation allowed)
__device__ uint8_t g_K8[(size_t)N * (size_t)N];    // 64 MB e4m3 K*256
__device__ uint8_t g_M8[(size_t)N * (size_t)N];    // 64 MB e4m3 K*c*16384
__device__ float g_spn[N];
__device__ float g_sqn[N];
__device__ float g_pp[2][8][N];                    // ping-pong column-split partials
__device__ float g_ppT[8][N];                      // final t-partials

__device__ __forceinline__ float sqrt_approx(float x) {
    float r;
    asm("sqrt.approx.f32 %0, %1;" : "=f"(r) : "f"(x));
    return r;
}
__device__ __forceinline__ uint32_t smem_u32(const void* p) {
    uint32_t a;
    asm("{ .reg .u64 t; cvta.to.shared.u64 t, %1; cvt.u32.u64 %0, t; }" : "=r"(a) : "l"(p));
    return a;
}
__device__ __forceinline__ uint16_t f2_e4m3x2(float hi, float lo) {
    uint16_t d;
    asm("cvt.rn.satfinite.e4m3x2.f32 %0, %1, %2;" : "=h"(d) : "f"(hi), "f"(lo));
    return d;
}

// m16n8k16 bf16 HMMA (build)
__device__ __forceinline__ void mma_bf16(float* d, const uint32_t* a, const uint32_t* b) {
    asm volatile(
        "mma.sync.aligned.m16n8k16.row.col.f32.bf16.bf16.f32 "
        "{%0,%1,%2,%3}, {%4,%5,%6,%7}, {%8,%9}, {%0,%1,%2,%3};"
        : "+f"(d[0]), "+f"(d[1]), "+f"(d[2]), "+f"(d[3])
        : "r"(a[0]), "r"(a[1]), "r"(a[2]), "r"(a[3]), "r"(b[0]), "r"(b[1]));
}
// m16n8k32 e4m3 MMA, fp32 accum
__device__ __forceinline__ void mma_e4m3(float* d, const uint32_t* a, uint32_t b0, uint32_t b1) {
    asm volatile(
        "mma.sync.aligned.m16n8k32.row.col.f32.e4m3.e4m3.f32 "
        "{%0,%1,%2,%3}, {%4,%5,%6,%7}, {%8,%9}, {%0,%1,%2,%3};"
        : "+f"(d[0]), "+f"(d[1]), "+f"(d[2]), "+f"(d[3])
        : "r"(a[0]), "r"(a[1]), "r"(a[2]), "r"(a[3]), "r"(b0), "r"(b1));
}

// ---------------------------------------------------------------------------
__global__ void norms_kernel(const float* __restrict__ P, const float* __restrict__ Q) {
    int w = (blockIdx.x * blockDim.x + threadIdx.x) >> 5;
    int lane = threadIdx.x & 31;
    if (w >= N) return;
    float2 p = reinterpret_cast<const float2*>(P)[w * 32 + lane];
    float s = p.x * p.x + p.y * p.y;
    float2 q = reinterpret_cast<const float2*>(Q)[w * 32 + lane];
    float t = q.x * q.x + q.y * q.y;
    #pragma unroll
    for (int o = 16; o > 0; o >>= 1) {
        s += __shfl_xor_sync(0xffffffffu, s, o);
        t += __shfl_xor_sync(0xffffffffu, t, o);
    }
    if (lane == 0) { g_spn[w] = s; g_sqn[w] = t; }
}

__global__ void init_pp() {
    int i = blockIdx.x * blockDim.x + threadIdx.x;
    if (i < N) {
        g_pp[0][0][i] = 64.0f;
        #pragma unroll
        for (int c = 1; c < 8; c++) g_pp[0][c][i] = 0.0f;
    }
}

// ---------------------------------------------------------------------------
// Build via mma.sync bf16; emit e4m3 K*256 (g_K8) and e4m3 K*c*16384 (g_M8).
// ---------------------------------------------------------------------------
#define AST 72
#define C8ST 144   // fp8 stage stride (bytes), 16-aligned
#define SCALE_M 16384.0f

__global__ void __launch_bounds__(256)
build_kernel(const float* __restrict__ P, const float* __restrict__ Q) {
    __shared__ float s_norm[256];
    __shared__ __align__(16) char s_tile[2 * 128 * AST * 2];   // 36864 B

    __nv_bfloat16* s_A = reinterpret_cast<__nv_bfloat16*>(s_tile);
    __nv_bfloat16* s_B = s_A + 128 * AST;

    const int tid = threadIdx.x;
    const int by = blockIdx.y, bx = blockIdx.x;

    if (tid < 128) s_norm[tid] = g_spn[by * 128 + tid];
    else           s_norm[tid] = g_sqn[bx * 128 + (tid - 128)];

    {
        const int row = tid >> 1, half = tid & 1;
        const float4* ps = reinterpret_cast<const float4*>(P + (size_t)(by * 128 + row) * D + half * 32);
        __nv_bfloat16* ad = s_A + row * AST + half * 32;
        #pragma unroll
        for (int s = 0; s < 4; s++) {
            float4 f0 = ps[2 * s], f1 = ps[2 * s + 1];
            __nv_bfloat162 hh[4];
            hh[0] = __floats2bfloat162_rn(f0.x, f0.y);
            hh[1] = __floats2bfloat162_rn(f0.z, f0.w);
            hh[2] = __floats2bfloat162_rn(f1.x, f1.y);
            hh[3] = __floats2bfloat162_rn(f1.z, f1.w);
            *reinterpret_cast<uint4*>(ad + s * 8) = *reinterpret_cast<uint4*>(hh);
        }
        const float4* qs = reinterpret_cast<const float4*>(Q + (size_t)(bx * 128 + row) * D + half * 32);
        __nv_bfloat16* bd = s_B + row * AST + half * 32;
        #pragma unroll
        for (int s = 0; s < 4; s++) {
            float4 f0 = qs[2 * s], f1 = qs[2 * s + 1];
            __nv_bfloat162 hh[4];
            hh[0] = __floats2bfloat162_rn(f0.x, f0.y);
            hh[1] = __floats2bfloat162_rn(f0.z, f0.w);
            hh[2] = __floats2bfloat162_rn(f1.x, f1.y);
            hh[3] = __floats2bfloat162_rn(f1.z, f1.w);
            *reinterpret_cast<uint4*>(bd + s * 8) = *reinterpret_cast<uint4*>(hh);
        }
    }
    __syncthreads();

    const int lane = tid & 31, wid = tid >> 5;
    const int g = lane >> 2, t = lane & 3;
    const int wm = (wid & 1) * 64;
    const int wn = (wid >> 1) * 32;

    float acc[4][4][4];
    #pragma unroll
    for (int mi = 0; mi < 4; mi++)
        #pragma unroll
        for (int nj = 0; nj < 4; nj++)
            #pragma unroll
            for (int e = 0; e < 4; e++) acc[mi][nj][e] = 0.0f;

    #pragma unroll
    for (int ks = 0; ks < 4; ks++) {
        const int kb = ks * 16 + t * 2;
        uint32_t afr[4][4];
        #pragma unroll
        for (int mi = 0; mi < 4; mi++) {
            const int r = wm + mi * 16 + g;
            afr[mi][0] = *reinterpret_cast<const uint32_t*>(s_A + r * AST + kb);
            afr[mi][1] = *reinterpret_cast<const uint32_t*>(s_A + (r + 8) * AST + kb);
            afr[mi][2] = *reinterpret_cast<const uint32_t*>(s_A + r * AST + kb + 8);
            afr[mi][3] = *reinterpret_cast<const uint32_t*>(s_A + (r + 8) * AST + kb + 8);
        }
        uint32_t bfr[4][2];
        #pragma unroll
        for (int nj = 0; nj < 4; nj++) {
            const int c = wn + nj * 8 + g;
            bfr[nj][0] = *reinterpret_cast<const uint32_t*>(s_B + c * AST + kb);
            bfr[nj][1] = *reinterpret_cast<const uint32_t*>(s_B + c * AST + kb + 8);
        }
        #pragma unroll
        for (int mi = 0; mi < 4; mi++)
            #pragma unroll
            for (int nj = 0; nj < 4; nj++)
                mma_bf16(acc[mi][nj], afr[mi], bfr[nj]);
    }

    __syncthreads();
    // Reuse A/B stage as two fp8 tile stages (2 x 18432 = 36864 B)
    char* s_c8 = s_tile;
    char* s_m8 = s_tile + 128 * C8ST;

    #pragma unroll
    for (int mi = 0; mi < 4; mi++) {
        const int r0 = wm + mi * 16 + g;
        const float spa = s_norm[r0];
        const float spb = s_norm[r0 + 8];
        #pragma unroll
        for (int nj = 0; nj < 4; nj++) {
            const int c0 = wn + nj * 8 + t * 2;
            const float sq0 = s_norm[128 + c0];
            const float sq1 = s_norm[128 + c0 + 1];
            const float* a = acc[mi][nj];
            float d0 = sqrt_approx(fmaxf(spa + sq0 - 2.0f * a[0], 0.0f));
            float d1 = sqrt_approx(fmaxf(spa + sq1 - 2.0f * a[1], 0.0f));
            float d2 = sqrt_approx(fmaxf(spb + sq0 - 2.0f * a[2], 0.0f));
            float d3 = sqrt_approx(fmaxf(spb + sq1 - 2.0f * a[3], 0.0f));
            float e0 = __expf(-INV_EPS * d0);
            float e1 = __expf(-INV_EPS * d1);
            float e2 = __expf(-INV_EPS * d2);
            float e3 = __expf(-INV_EPS * d3);
            *reinterpret_cast<uint16_t*>(s_c8 + r0 * C8ST + c0)       = f2_e4m3x2(e1 * 256.0f, e0 * 256.0f);
            *reinterpret_cast<uint16_t*>(s_c8 + (r0 + 8) * C8ST + c0) = f2_e4m3x2(e3 * 256.0f, e2 * 256.0f);
            *reinterpret_cast<uint16_t*>(s_m8 + r0 * C8ST + c0)       = f2_e4m3x2(e1 * d1 * SCALE_M, e0 * d0 * SCALE_M);
            *reinterpret_cast<uint16_t*>(s_m8 + (r0 + 8) * C8ST + c0) = f2_e4m3x2(e3 * d3 * SCALE_M, e2 * d2 * SCALE_M);
        }
    }
    __syncthreads();

    // Store both fp8 tiles: 1024 uint4 each
    #pragma unroll
    for (int i = 0; i < 4; i++) {
        const int idx = i * 256 + tid;
        const int r = idx >> 3, seg = idx & 7;
        uint4 vk = *reinterpret_cast<uint4*>(s_c8 + r * C8ST + seg * 16);
        *reinterpret_cast<uint4*>(g_K8 + (size_t)(by * 128 + r) * N + bx * 128 + seg * 16) = vk;
        uint4 vm = *reinterpret_cast<uint4*>(s_m8 + r * C8ST + seg * 16);
        *reinterpret_cast<uint4*>(g_M8 + (size_t)(by * 128 + r) * N + bx * 128 + seg * 16) = vm;
    }
}

// ---------------------------------------------------------------------------
// fp8 tensor-core matvec on K8 (validated R12). CTA = 4 warps x 16 rows,
// column split 1/8. Chunk = 16 rows x 128 fp8, 4 k-steps of 32.
// ---------------------------------------------------------------------------
#define CSPLIT 8
#define MV_COLS (N / CSPLIT)        // 1024
#define MV_NCHUNK (MV_COLS / 128)   // 8
#define STAGES 4

__global__ void __launch_bounds__(128, 6) matvec_kernel(int src, int dst) {
    __shared__ __align__(16) uint8_t xh8[MV_COLS];
    __shared__ __align__(16) uint8_t tiles[4][STAGES][16 * 128]; // 32 KB

    const int tid = threadIdx.x;
    const int lane = tid & 31, w = tid >> 5;
    const int cs = blockIdx.x, rb = blockIdx.y;
    const int grow = rb * 64 + w * 16;
    const int colbase = cs * MV_COLS;

    #pragma unroll
    for (int i = tid; i < MV_COLS / 4; i += 128) {
        const int f4 = cs * (MV_COLS / 4) + i;
        float4 sum = reinterpret_cast<const float4*>(g_pp[src][0])[f4];
        #pragma unroll
        for (int c = 1; c < CSPLIT; c++) {
            float4 p = reinterpret_cast<const float4*>(g_pp[src][c])[f4];
            sum.x += p.x; sum.y += p.y; sum.z += p.z; sum.w += p.w;
        }
        uint16_t lo = f2_e4m3x2(64.0f / sum.y, 64.0f / sum.x);
        uint16_t hi = f2_e4m3x2(64.0f / sum.w, 64.0f / sum.z);
        reinterpret_cast<uint32_t*>(xh8)[i] = (uint32_t)lo | ((uint32_t)hi << 16);
    }

    const int c16 = lane & 7;
    const int rquad = lane >> 3;
    const uint32_t tbase = smem_u32(&tiles[w][0][0]);
    const char* gsrc[4];
    uint32_t dstoff[4];
    #pragma unroll
    for (int i = 0; i < 4; i++) {
        const int rl = i * 4 + rquad;
        gsrc[i] = reinterpret_cast<const char*>(g_K8 + (size_t)(grow + rl) * N + colbase + c16 * 16);
        dstoff[i] = rl * 128 + ((c16 ^ (rl & 7)) * 16);
    }

    const int lm_m = lane >> 3, lm_r = lane & 7;
    const int lrow = lm_r + (lm_m & 1) * 8;
    const int khalf = lm_m >> 1;

    const int g = lane >> 2, t = lane & 3;
    float acc[4] = {0.0f, 0.0f, 0.0f, 0.0f};

    __syncthreads();

    #pragma unroll
    for (int s = 0; s < STAGES - 1; s++) {
        #pragma unroll
        for (int i = 0; i < 4; i++)
            asm volatile("cp.async.cg.shared.global [%0], [%1], 16;"
                         :: "r"(tbase + s * 2048 + dstoff[i]), "l"(gsrc[i] + s * 128) : "memory");
        asm volatile("cp.async.commit_group;" ::: "memory");
    }

    for (int ch = 0; ch < MV_NCHUNK; ch++) {
        asm volatile("cp.async.wait_group %0;" :: "n"(STAGES - 2) : "memory");
        __syncthreads();

        const uint32_t stbase = tbase + (ch & (STAGES - 1)) * 2048;
        const int xb = ch * 128;
        #pragma unroll
        for (int s4 = 0; s4 < 4; s4++) {
            const int cc = 2 * s4 + khalf;
            uint32_t a[4];
            asm volatile("ldmatrix.sync.aligned.m8n8.x4.shared.b16 {%0,%1,%2,%3}, [%4];"
                         : "=r"(a[0]), "=r"(a[1]), "=r"(a[2]), "=r"(a[3])
                         : "r"(stbase + lrow * 128 + ((cc ^ (lrow & 7)) * 16)));
            uint32_t b0 = *reinterpret_cast<const uint32_t*>(&xh8[xb + s4 * 32 + t * 4]);
            uint32_t b1 = *reinterpret_cast<const uint32_t*>(&xh8[xb + s4 * 32 + t * 4 + 16]);
            mma_e4m3(acc, a, b0, b1);
        }

        const int nch = ch + STAGES - 1;
        if (nch < MV_NCHUNK) {
            const uint32_t ns = tbase + (nch & (STAGES - 1)) * 2048;
            #pragma unroll
            for (int i = 0; i < 4; i++)
                asm volatile("cp.async.cg.shared.global [%0], [%1], 16;"
                             :: "r"(ns + dstoff[i]), "l"(gsrc[i] + nch * 128) : "memory");
        }
        asm volatile("cp.async.commit_group;" ::: "memory");
    }

    if (t == 0) {
        const float s = 1.0f / 16384.0f;
        g_pp[dst][cs][grow + g]     = acc[0] * s;
        g_pp[dst][cs][grow + g + 8] = acc[2] * s;
    }
}

// ---------------------------------------------------------------------------
// Final dual fp8 tensor matvec: raw_s = sum K8 v, raw_t = sum M8 v.
// Writes partials; sum_final computes loss = sum_i (raw_t/raw_s)/64.
// ---------------------------------------------------------------------------
__global__ void __launch_bounds__(128) final_mv(int src) {
    __shared__ __align__(16) uint8_t xh8[MV_COLS];
    __shared__ __align__(16) uint8_t tiles[4][STAGES][2][16 * 128]; // 64 KB

    const int tid = threadIdx.x;
    const int lane = tid & 31, w = tid >> 5;
    const int cs = blockIdx.x, rb = blockIdx.y;
    const int grow = rb * 64 + w * 16;
    const int colbase = cs * MV_COLS;

    #pragma unroll
    for (int i = tid; i < MV_COLS / 4; i += 128) {
        const int f4 = cs * (MV_COLS / 4) + i;
        float4 sum = reinterpret_cast<const float4*>(g_pp[src][0])[f4];
        #pragma unroll
        for (int c = 1; c < CSPLIT; c++) {
            float4 p = reinterpret_cast<const float4*>(g_pp[src][c])[f4];
            sum.x += p.x; sum.y += p.y; sum.z += p.z; sum.w += p.w;
        }
        uint16_t lo = f2_e4m3x2(64.0f / sum.y, 64.0f / sum.x);
        uint16_t hi = f2_e4m3x2(64.0f / sum.w, 64.0f / sum.z);
        reinterpret_cast<uint32_t*>(xh8)[i] = (uint32_t)lo | ((uint32_t)hi << 16);
    }

    const int c16 = lane & 7;
    const int rquad = lane >> 3;
    const uint32_t tbase = smem_u32(&tiles[w][0][0][0]);
    const char* gsK[4];
    const char* gsM[4];
    uint32_t dstoff[4];
    #pragma unroll
    for (int i = 0; i < 4; i++) {
        const int rl = i * 4 + rquad;
        gsK[i] = reinterpret_cast<const char*>(g_K8 + (size_t)(grow + rl) * N + colbase + c16 * 16);
        gsM[i] = reinterpret_cast<const char*>(g_M8 + (size_t)(grow + rl) * N + colbase + c16 * 16);
        dstoff[i] = rl * 128 + ((c16 ^ (rl & 7)) * 16);
    }

    const int lm_m = lane >> 3, lm_r = lane & 7;
    const int lrow = lm_r + (lm_m & 1) * 8;
    const int khalf = lm_m >> 1;

    const int g = lane >> 2, t = lane & 3;
    float accS[4] = {0.0f, 0.0f, 0.0f, 0.0f};
    float accT[4] = {0.0f, 0.0f, 0.0f, 0.0f};

    __syncthreads();

    #pragma unroll
    for (int s = 0; s < STAGES - 1; s++) {
        #pragma unroll
        for (int i = 0; i < 4; i++)
            asm volatile("cp.async.cg.shared.global [%0], [%1], 16;"
                         :: "r"(tbase + s * 4096 + dstoff[i]), "l"(gsK[i] + s * 128) : "memory");
        #pragma unroll
        for (int i = 0; i < 4; i++)
            asm volatile("cp.async.cg.shared.global [%0], [%1], 16;"
                         :: "r"(tbase + s * 4096 + 2048 + dstoff[i]), "l"(gsM[i] + s * 128) : "memory");
        asm volatile("cp.async.commit_group;" ::: "memory");
    }

    for (int ch = 0; ch < MV_NCHUNK; ch++) {
        asm volatile("cp.async.wait_group %0;" :: "n"(STAGES - 2) : "memory");
        __syncthreads();

        const uint32_t stbase = tbase + (ch & (STAGES - 1)) * 4096;
        const int xb = ch * 128;
        #pragma unroll
        for (int s4 = 0; s4 < 4; s4++) {
            const int cc = 2 * s4 + khalf;
            const uint32_t lmoff = lrow * 128 + ((cc ^ (lrow & 7)) * 16);
            uint32_t b0 = *reinterpret_cast<const uint32_t*>(&xh8[xb + s4 * 32 + t * 4]);
            uint32_t b1 = *reinterpret_cast<const uint32_t*>(&xh8[xb + s4 * 32 + t * 4 + 16]);
            uint32_t a[4];
            asm volatile("ldmatrix.sync.aligned.m8n8.x4.shared.b16 {%0,%1,%2,%3}, [%4];"
                         : "=r"(a[0]), "=r"(a[1]), "=r"(a[2]), "=r"(a[3])
                         : "r"(stbase + lmoff));
            mma_e4m3(accS, a, b0, b1);
            uint32_t m[4];
            asm volatile("ldmatrix.sync.aligned.m8n8.x4.shared.b16 {%0,%1,%2,%3}, [%4];"
                         : "=r"(m[0]), "=r"(m[1]), "=r"(m[2]), "=r"(m[3])
                         : "r"(stbase + 2048 + lmoff));
            mma_e4m3(accT, m, b0, b1);
        }

        const int nch = ch + STAGES - 1;
        if (nch < MV_NCHUNK) {
            const uint32_t ns = tbase + (nch & (STAGES - 1)) * 4096;
            #pragma unroll
            for (int i = 0; i < 4; i++)
                asm volatile("cp.async.cg.shared.global [%0], [%1], 16;"
                             :: "r"(ns + dstoff[i]), "l"(gsK[i] + nch * 128) : "memory");
            #pragma unroll
            for (int i = 0; i < 4; i++)
                asm volatile("cp.async.cg.shared.global [%0], [%1], 16;"
                             :: "r"(ns + 2048 + dstoff[i]), "l"(gsM[i] + nch * 128) : "memory");
        }
        asm volatile("cp.async.commit_group;" ::: "memory");
    }

    if (t == 0) {
        g_pp[0][cs][grow + g]     = accS[0];   // raw s partials (pp[0] is dead)
        g_pp[0][cs][grow + g + 8] = accS[2];
        g_ppT[cs][grow + g]       = accT[0];
        g_ppT[cs][grow + g + 8]   = accT[2];
    }
}

// loss = sum_i (sum_cs t / sum_cs s) / 64
__global__ void sum_final(float* __restrict__ out) {
    const int tid = threadIdx.x;   // 1024
    float a = 0.0f;
    for (int row = tid; row < N; row += 1024) {
        float s = 0.0f, t = 0.0f;
        #pragma unroll
        for (int c = 0; c < CSPLIT; c++) {
            s += g_pp[0][c][row];
            t += g_ppT[c][row];
        }
        a += t / (s * 64.0f);
    }
    __shared__ float sm[32];
    #pragma unroll
    for (int o = 16; o > 0; o >>= 1) a += __shfl_xor_sync(0xffffffffu, a, o);
    if ((tid & 31) == 0) sm[tid >> 5] = a;
    __syncthreads();
    if (tid == 0) {
        float total = 0.0f;
        #pragma unroll
        for (int w = 0; w < 32; w++) total += sm[w];
        out[0] = total;
    }
}

// ---------------------------------------------------------------------------
extern "C" void kernel_launch(void* const* d_in, const int* in_sizes, int n_in,
                              void* d_out, int out_size) {
    (void)in_sizes; (void)n_in; (void)out_size;
    const float* P = (const float*)d_in[0];
    const float* Q = (const float*)d_in[1];
    float* out = (float*)d_out;

    norms_kernel<<<N / 8, 256>>>(P, Q);
    init_pp<<<N / 256, 256>>>();
    build_kernel<<<dim3(N / 128, N / 128), 256>>>(P, Q);

    for (int li = 0; li < 9; li++)
        matvec_kernel<<<dim3(CSPLIT, N / 64), 128>>>(li & 1, (li + 1) & 1);

    final_mv<<<dim3(CSPLIT, N / 64), 128>>>(1);
    sum_final<<<1, 1024>>>(out);
}